// round 17
// baseline (speedup 1.0000x reference)
#include <cuda_runtime.h>
#include <cuda_bf16.h>
#include <cuda_fp16.h>
#include <math.h>
#include <stdint.h>

#define NN    50000
#define EE    800000
#define ETOT  (EE + NN)     // edges + self loops
#define HH    4
#define CC    32
#define HC    128
#define NHID  512
#define NOUT  768
#define GG    256

#define SPAD  136           // smem row stride (fp16 elems), conflict-free

// ---------------- scratch (device globals; no allocation allowed) ----------
__device__ __half g_hf[NN * HC];    // h = x @ W, fp16 (gather payload)
__device__ float g_sk[NN * HC];     // skip = x @ skW
__device__ float g_x [NN * HC];     // layer output / next input
__device__ float g_esrc[NN * HH];
__device__ float g_edst[NN * HH];
__device__ int   g_deg[NN];
__device__ int   g_cnt[NN];
__device__ int   g_off[NN + 1];
__device__ int   g_srcidx[ETOT];
__device__ int   g_bsum[64];
__device__ int   g_bpre[64];
__device__ float g_pool[GG * HC];
__device__ float g_hid [GG * NHID];
__device__ int   g_is64;
// transposed + split GAT weights: index 2L = W, 2L+1 = skW; layout [n][k], fp16 hi/lo
__device__ __half g_wthi[6 * 128 * 128];
__device__ __half g_wtlo[6 * 128 * 128];
// transposed + split MLP weights: [n][k] layout
__device__ __half g_m1hi[NHID * HC];
__device__ __half g_m1lo[NHID * HC];
__device__ __half g_m2hi[NOUT * NHID];
__device__ __half g_m2lo[NOUT * NHID];

// ---------------- dtype detection for edge_index / batch -------------------
__global__ void detect_k(const unsigned* __restrict__ w) {
    int all0 = 1;
    for (int i = 0; i < 256; ++i)
        if (w[2 * i + 1] != 0u) { all0 = 0; break; }
    g_is64 = all0;
}

__device__ __forceinline__ int fetch_idx(const void* p, long i, int is64) {
    if (is64) return (int)((const long long*)p)[i];
    return ((const int*)p)[i];
}

// ---------------- init ------------------------------------------------------
__global__ void init_k() {
    int i = blockIdx.x * blockDim.x + threadIdx.x;
    if (i < NN) { g_deg[i] = 1; g_cnt[i] = 0; }
    if (i < GG * HC) g_pool[i] = 0.0f;
}

__global__ void hist_k(const void* __restrict__ ei) {
    int e = blockIdx.x * blockDim.x + threadIdx.x;
    if (e >= EE) return;
    int is64 = g_is64;
    int d = fetch_idx(ei, (long)EE + e, is64);
    atomicAdd(&g_deg[d], 1);
}

__global__ void scan1_k() {
    __shared__ int sh[1024];
    int t = threadIdx.x;
    int i = blockIdx.x * 1024 + t;
    int v = (i < NN) ? g_deg[i] : 0;
    sh[t] = v;
    for (int off = 1; off < 1024; off <<= 1) {
        __syncthreads();
        int x = (t >= off) ? sh[t - off] : 0;
        __syncthreads();
        sh[t] += x;
    }
    __syncthreads();
    if (i < NN) g_off[i] = sh[t];
    if (t == 1023) g_bsum[blockIdx.x] = sh[1023];
}

__global__ void scan2_k(int nblk) {
    if (threadIdx.x == 0) {
        int acc = 0;
        for (int b = 0; b < nblk; ++b) { g_bpre[b] = acc; acc += g_bsum[b]; }
    }
}

__global__ void scan3_k() {
    int t = threadIdx.x;
    int i = blockIdx.x * 1024 + t;
    if (i < NN) g_off[i] = g_off[i] + g_bpre[blockIdx.x] - g_deg[i];
    if (i == 0) g_off[NN] = ETOT;
}

__global__ void scatter_k(const void* __restrict__ ei) {
    long idx = (long)blockIdx.x * blockDim.x + threadIdx.x;
    if (idx >= ETOT) return;
    int is64 = g_is64;
    int s, d;
    if (idx < EE) {
        s = fetch_idx(ei, idx, is64);
        d = fetch_idx(ei, (long)EE + idx, is64);
    } else {
        s = d = (int)(idx - EE);
    }
    int p = g_off[d] + atomicAdd(&g_cnt[d], 1);
    g_srcidx[p] = s;
}

// ---------------- weight prep: transpose + split into fp16 hi/lo ------------
__global__ void prep_w_k(const float* w0, const float* w1, const float* w2,
                         const float* w3, const float* w4, const float* w5) {
    const float* src[6] = {w0, w1, w2, w3, w4, w5};
    int b = blockIdx.x;
    const float* W = src[b];
    __half* hi = g_wthi + b * 16384;
    __half* lo = g_wtlo + b * 16384;
    for (int idx = threadIdx.x; idx < 16384; idx += blockDim.x) {
        int n = idx >> 7, k = idx & 127;
        float x = W[k * 128 + n];            // transpose: [n][k] <- W[k][n]
        __half h = __float2half(x);
        float r = x - __half2float(h);
        hi[idx] = h;
        lo[idx] = __float2half(r);
    }
}

__global__ void prep_mlp_k(const float* __restrict__ m1w, const float* __restrict__ m2w) {
    int b = blockIdx.x;   // 8 blocks: 0 -> m1, 1..7 -> m2
    if (b == 0) {
        for (int idx = threadIdx.x; idx < NHID * HC; idx += blockDim.x) {
            int n = idx >> 7, k = idx & 127;
            float x = m1w[k * NHID + n];
            __half h = __float2half(x);
            g_m1hi[idx] = h;
            g_m1lo[idx] = __float2half(x - __half2float(h));
        }
    } else {
        for (int idx = (b - 1) * (int)blockDim.x + threadIdx.x; idx < NOUT * NHID;
             idx += 7 * (int)blockDim.x) {
            int n = idx / NHID, k = idx % NHID;
            float x = m2w[(size_t)k * NOUT + n];
            __half h = __float2half(x);
            g_m2hi[idx] = h;
            g_m2lo[idx] = __float2half(x - __half2float(h));
        }
    }
}

// ---------------- mma helpers ------------------------------------------------
__device__ __forceinline__ void mma16816(float* c, const uint32_t* a, const uint32_t* b) {
    asm volatile(
        "mma.sync.aligned.m16n8k16.row.col.f32.f16.f16.f32 "
        "{%0,%1,%2,%3}, {%4,%5,%6,%7}, {%8,%9}, {%0,%1,%2,%3};"
        : "+f"(c[0]), "+f"(c[1]), "+f"(c[2]), "+f"(c[3])
        : "r"(a[0]), "r"(a[1]), "r"(a[2]), "r"(a[3]), "r"(b[0]), "r"(b[1]));
}

__device__ __forceinline__ void ldsm4(uint32_t* r, uint32_t addr) {
    asm volatile(
        "ldmatrix.sync.aligned.m8n8.x4.shared.b16 {%0,%1,%2,%3}, [%4];"
        : "=r"(r[0]), "=r"(r[1]), "=r"(r[2]), "=r"(r[3]) : "r"(addr));
}

// ---------------- 2-term fp16 GAT GEMM (ldmatrix) + fused attention ---------
// dynamic smem layout (bytes; extern shared is 16B-aligned):
// A[0,34816) Bhi[34816,69632) Blo[69632,104448) sas[104448,104960) sad[104960,105472)
#define SM_BHI 34816
#define SM_BLO 69632
#define SM_SAS 104448
#define SM_SAD 104960
#define SM_TOT 105472

__global__ __launch_bounds__(256, 2)
void gemm_mma_k(const float* __restrict__ A,
                const __half* __restrict__ B0hi, const __half* __restrict__ B0lo,
                const __half* __restrict__ B1hi, const __half* __restrict__ B1lo,
                const float* __restrict__ as_, const float* __restrict__ ad_, int M) {
    extern __shared__ char smraw[];
    __half* sA   = (__half*)smraw;
    __half* sBhi = (__half*)(smraw + SM_BHI);
    __half* sBlo = (__half*)(smraw + SM_BLO);
    float* sas = (float*)(smraw + SM_SAS);
    float* sad = (float*)(smraw + SM_SAD);

    const __half* Bhi = blockIdx.y ? B1hi : B0hi;
    const __half* Blo = blockIdx.y ? B1lo : B0lo;

    int tid = threadIdx.x;
    int m0 = blockIdx.x * 128;

    if (tid < 128) { sas[tid] = as_[tid]; sad[tid] = ad_[tid]; }

    union P8 { __half b[8]; uint4 u; };
#pragma unroll
    for (int it = 0; it < 8; ++it) {
        int idx = tid + it * 256;
        int row = idx >> 4;
        int col = (idx & 15) * 8;
        float4 a0 = make_float4(0.f, 0.f, 0.f, 0.f), a1 = a0;
        if (m0 + row < M) {
            a0 = *(const float4*)&A[(size_t)(m0 + row) * 128 + col];
            a1 = *(const float4*)&A[(size_t)(m0 + row) * 128 + col + 4];
        }
        P8 ph;
        ph.b[0] = __float2half(a0.x); ph.b[1] = __float2half(a0.y);
        ph.b[2] = __float2half(a0.z); ph.b[3] = __float2half(a0.w);
        ph.b[4] = __float2half(a1.x); ph.b[5] = __float2half(a1.y);
        ph.b[6] = __float2half(a1.z); ph.b[7] = __float2half(a1.w);
        *(uint4*)&sA[row * SPAD + col] = ph.u;
        *(uint4*)&sBhi[row * SPAD + col] = *(const uint4*)&Bhi[(size_t)row * 128 + col];
        *(uint4*)&sBlo[row * SPAD + col] = *(const uint4*)&Blo[(size_t)row * 128 + col];
    }
    __syncthreads();

    int w = tid >> 5, lane = tid & 31;
    int mw = (w >> 1) * 32, nw = (w & 1) * 64;
    int gr = lane >> 2;
    int c2 = (lane & 3) * 2;

    int laneq = lane >> 3, laner = lane & 7;
    int aRow = mw + ((laneq & 1) << 3) + laner;
    int aCol = (laneq >> 1) << 3;
    int bRow = nw + ((laneq >> 1) << 3) + laner;
    int bCol = (laneq & 1) << 3;

    uint32_t sAaddr   = (uint32_t)__cvta_generic_to_shared(sA);
    uint32_t sBhiaddr = (uint32_t)__cvta_generic_to_shared(sBhi);
    uint32_t sBloaddr = (uint32_t)__cvta_generic_to_shared(sBlo);

    float acc[2][8][4];
#pragma unroll
    for (int i = 0; i < 2; ++i)
#pragma unroll
        for (int j = 0; j < 8; ++j)
#pragma unroll
            for (int q = 0; q < 4; ++q) acc[i][j][q] = 0.f;

#pragma unroll
    for (int ks = 0; ks < 8; ++ks) {
        int k0 = ks * 16;
        uint32_t a0[4], a1[4];
        ldsm4(a0, sAaddr + 2u * ((aRow)      * SPAD + k0 + aCol));
        ldsm4(a1, sAaddr + 2u * ((aRow + 16) * SPAD + k0 + aCol));
#pragma unroll
        for (int ntp = 0; ntp < 4; ++ntp) {
            uint32_t bh[4], bl[4];
            uint32_t boff = 2u * ((bRow + ntp * 16) * SPAD + k0 + bCol);
            ldsm4(bh, sBhiaddr + boff);
            ldsm4(bl, sBloaddr + boff);
            int nt = ntp * 2;
            mma16816(acc[0][nt],     a0, bh);     mma16816(acc[0][nt],     a0, bl);
            mma16816(acc[0][nt + 1], a0, bh + 2); mma16816(acc[0][nt + 1], a0, bl + 2);
            mma16816(acc[1][nt],     a1, bh);     mma16816(acc[1][nt],     a1, bl);
            mma16816(acc[1][nt + 1], a1, bh + 2); mma16816(acc[1][nt + 1], a1, bl + 2);
        }
    }

    if (blockIdx.y == 0) {
#pragma unroll
        for (int mt = 0; mt < 2; ++mt) {
            int r0 = m0 + mw + mt * 16 + gr;
            int r1 = r0 + 8;
#pragma unroll
            for (int nt = 0; nt < 8; ++nt) {
                int cc = nw + nt * 8 + c2;
                if (r0 < M)
                    *(__half2*)&g_hf[(size_t)r0 * 128 + cc] =
                        __floats2half2_rn(acc[mt][nt][0], acc[mt][nt][1]);
                if (r1 < M)
                    *(__half2*)&g_hf[(size_t)r1 * 128 + cc] =
                        __floats2half2_rn(acc[mt][nt][2], acc[mt][nt][3]);
            }
        }
        int h0 = (w & 1) * 2;
#pragma unroll
        for (int mt = 0; mt < 2; ++mt) {
#pragma unroll
            for (int hh = 0; hh < 2; ++hh) {
                float ps0 = 0.f, pd0 = 0.f, ps1 = 0.f, pd1 = 0.f;
#pragma unroll
                for (int q = 0; q < 4; ++q) {
                    int nt = hh * 4 + q;
                    int cc = nw + nt * 8 + c2;
                    float a0f = sas[cc], a1f = sas[cc + 1];
                    float d0f = sad[cc], d1f = sad[cc + 1];
                    ps0 += acc[mt][nt][0] * a0f + acc[mt][nt][1] * a1f;
                    pd0 += acc[mt][nt][0] * d0f + acc[mt][nt][1] * d1f;
                    ps1 += acc[mt][nt][2] * a0f + acc[mt][nt][3] * a1f;
                    pd1 += acc[mt][nt][2] * d0f + acc[mt][nt][3] * d1f;
                }
#pragma unroll
                for (int off = 1; off <= 2; off <<= 1) {
                    ps0 += __shfl_xor_sync(0xffffffffu, ps0, off);
                    pd0 += __shfl_xor_sync(0xffffffffu, pd0, off);
                    ps1 += __shfl_xor_sync(0xffffffffu, ps1, off);
                    pd1 += __shfl_xor_sync(0xffffffffu, pd1, off);
                }
                if ((lane & 3) == 0) {
                    int head = h0 + hh;
                    int r0 = m0 + mw + mt * 16 + gr;
                    int r1 = r0 + 8;
                    if (r0 < M) { g_esrc[r0 * HH + head] = ps0; g_edst[r0 * HH + head] = pd0; }
                    if (r1 < M) { g_esrc[r1 * HH + head] = ps1; g_edst[r1 * HH + head] = pd1; }
                }
            }
        }
    } else {
#pragma unroll
        for (int mt = 0; mt < 2; ++mt) {
            int r0 = m0 + mw + mt * 16 + gr;
            int r1 = r0 + 8;
#pragma unroll
            for (int nt = 0; nt < 8; ++nt) {
                int cc = nw + nt * 8 + c2;
                if (r0 < M)
                    *(float2*)&g_sk[(size_t)r0 * 128 + cc] =
                        make_float2(acc[mt][nt][0], acc[mt][nt][1]);
                if (r1 < M)
                    *(float2*)&g_sk[(size_t)r1 * 128 + cc] =
                        make_float2(acc[mt][nt][2], acc[mt][nt][3]);
            }
        }
    }
}

// ---------------- 3-term fp16 MLP GEMM: C = [relu](A @ B^T + bias) ----------
// A [M,K] fp32; B [N,K] fp16 hi/lo ([n][k] layout). M,N,K multiples of 128.
// smem: Ahi, Alo, Bhi, Blo tiles (128 x SPAD fp16 each) = 139264 bytes.
#define SMM_ALO 34816
#define SMM_BHI 69632
#define SMM_BLO 104448
#define SMM_TOT 139264

__global__ __launch_bounds__(256, 1)
void mlp_gemm_k(const float* __restrict__ A,
                const __half* __restrict__ Bhi, const __half* __restrict__ Blo,
                const float* __restrict__ bias, float* __restrict__ C,
                int M, int N, int K, int relu) {
    extern __shared__ char smraw[];
    __half* sAhi = (__half*)smraw;
    __half* sAlo = (__half*)(smraw + SMM_ALO);
    __half* sBhi = (__half*)(smraw + SMM_BHI);
    __half* sBlo = (__half*)(smraw + SMM_BLO);

    int tid = threadIdx.x;
    int m0 = blockIdx.x * 128;
    int n0 = blockIdx.y * 128;

    int w = tid >> 5, lane = tid & 31;
    int mw = (w >> 1) * 32, nw = (w & 1) * 64;
    int gr = lane >> 2;
    int c2 = (lane & 3) * 2;

    int laneq = lane >> 3, laner = lane & 7;
    int aRow = mw + ((laneq & 1) << 3) + laner;
    int aCol = (laneq >> 1) << 3;
    int bRow = nw + ((laneq >> 1) << 3) + laner;
    int bCol = (laneq & 1) << 3;

    uint32_t sAhiaddr = (uint32_t)__cvta_generic_to_shared(sAhi);
    uint32_t sAloaddr = (uint32_t)__cvta_generic_to_shared(sAlo);
    uint32_t sBhiaddr = (uint32_t)__cvta_generic_to_shared(sBhi);
    uint32_t sBloaddr = (uint32_t)__cvta_generic_to_shared(sBlo);

    float acc[2][8][4];
#pragma unroll
    for (int i = 0; i < 2; ++i)
#pragma unroll
        for (int j = 0; j < 8; ++j)
#pragma unroll
            for (int q = 0; q < 4; ++q) acc[i][j][q] = 0.f;

    union P8 { __half b[8]; uint4 u; };

    for (int kc = 0; kc < K; kc += 128) {
        // ---- stage A chunk (fp32 -> fp16 hi/lo) and B chunk ----
#pragma unroll
        for (int it = 0; it < 8; ++it) {
            int idx = tid + it * 256;
            int row = idx >> 4;
            int col = (idx & 15) * 8;
            float4 a0 = make_float4(0.f, 0.f, 0.f, 0.f), a1 = a0;
            if (m0 + row < M) {
                a0 = *(const float4*)&A[(size_t)(m0 + row) * K + kc + col];
                a1 = *(const float4*)&A[(size_t)(m0 + row) * K + kc + col + 4];
            }
            float f[8] = {a0.x, a0.y, a0.z, a0.w, a1.x, a1.y, a1.z, a1.w};
            P8 ph, pl;
#pragma unroll
            for (int j = 0; j < 8; ++j) {
                __half hb = __float2half(f[j]);
                ph.b[j] = hb;
                pl.b[j] = __float2half(f[j] - __half2float(hb));
            }
            *(uint4*)&sAhi[row * SPAD + col] = ph.u;
            *(uint4*)&sAlo[row * SPAD + col] = pl.u;
            *(uint4*)&sBhi[row * SPAD + col] =
                *(const uint4*)&Bhi[(size_t)(n0 + row) * K + kc + col];
            *(uint4*)&sBlo[row * SPAD + col] =
                *(const uint4*)&Blo[(size_t)(n0 + row) * K + kc + col];
        }
        __syncthreads();

#pragma unroll
        for (int ks = 0; ks < 8; ++ks) {
            int k0 = ks * 16;
            uint32_t ah0[4], ah1[4], al0[4], al1[4];
            ldsm4(ah0, sAhiaddr + 2u * ((aRow)      * SPAD + k0 + aCol));
            ldsm4(ah1, sAhiaddr + 2u * ((aRow + 16) * SPAD + k0 + aCol));
            ldsm4(al0, sAloaddr + 2u * ((aRow)      * SPAD + k0 + aCol));
            ldsm4(al1, sAloaddr + 2u * ((aRow + 16) * SPAD + k0 + aCol));
#pragma unroll
            for (int ntp = 0; ntp < 4; ++ntp) {
                uint32_t bh[4], bl[4];
                uint32_t boff = 2u * ((bRow + ntp * 16) * SPAD + k0 + bCol);
                ldsm4(bh, sBhiaddr + boff);
                ldsm4(bl, sBloaddr + boff);
                int nt = ntp * 2;
                mma16816(acc[0][nt],     ah0, bh);     mma16816(acc[0][nt],     al0, bh);
                mma16816(acc[0][nt],     ah0, bl);
                mma16816(acc[0][nt + 1], ah0, bh + 2); mma16816(acc[0][nt + 1], al0, bh + 2);
                mma16816(acc[0][nt + 1], ah0, bl + 2);
                mma16816(acc[1][nt],     ah1, bh);     mma16816(acc[1][nt],     al1, bh);
                mma16816(acc[1][nt],     ah1, bl);
                mma16816(acc[1][nt + 1], ah1, bh + 2); mma16816(acc[1][nt + 1], al1, bh + 2);
                mma16816(acc[1][nt + 1], ah1, bl + 2);
            }
        }
        __syncthreads();
    }

    // ---- epilogue: bias (+ relu), write fp32 ----
#pragma unroll
    for (int mt = 0; mt < 2; ++mt) {
        int r0 = m0 + mw + mt * 16 + gr;
        int r1 = r0 + 8;
#pragma unroll
        for (int nt = 0; nt < 8; ++nt) {
            int cc = n0 + nw + nt * 8 + c2;
            float b0 = bias[cc], b1 = bias[cc + 1];
            float v00 = acc[mt][nt][0] + b0, v01 = acc[mt][nt][1] + b1;
            float v10 = acc[mt][nt][2] + b0, v11 = acc[mt][nt][3] + b1;
            if (relu) {
                v00 = fmaxf(v00, 0.f); v01 = fmaxf(v01, 0.f);
                v10 = fmaxf(v10, 0.f); v11 = fmaxf(v11, 0.f);
            }
            if (r0 < M) *(float2*)&C[(size_t)r0 * N + cc] = make_float2(v00, v01);
            if (r1 < M) *(float2*)&C[(size_t)r1 * N + cc] = make_float2(v10, v11);
        }
    }
}

// ---------------- warp-per-node softmax aggregation (shuffled srcidx) -------
__global__ void aggregate_k(const float* __restrict__ bias,
                            const float* __restrict__ skb) {
    int warp = (blockIdx.x * blockDim.x + threadIdx.x) >> 5;
    int lane = threadIdx.x & 31;
    if (warp >= NN) return;
    int n = warp;
    int head = lane >> 3;
    float ed = g_edst[n * HH + head];
    int j0 = g_off[n], j1 = g_off[n + 1];
    int cnt = j1 - j0;
    float z = 0.f;
    float4 acc = make_float4(0.f, 0.f, 0.f, 0.f);
    for (int base = 0; base < cnt; base += 32) {
        int sv = 0;
        if (base + lane < cnt) sv = g_srcidx[j0 + base + lane];
        int lim = cnt - base; if (lim > 32) lim = 32;
        for (int e = 0; e < lim; ++e) {
            int s = __shfl_sync(0xffffffffu, sv, e);
            float ev = g_esrc[s * HH + head] + ed;
            ev = (ev > 0.f) ? ev : 0.2f * ev;
            float wgt = __expf(ev);
            uint2 hp = *(const uint2*)&g_hf[(size_t)s * 128 + lane * 4];
            float2 f0 = __half22float2(*(const __half2*)&hp.x);
            float2 f1 = __half22float2(*(const __half2*)&hp.y);
            acc.x += wgt * f0.x;
            acc.y += wgt * f0.y;
            acc.z += wgt * f1.x;
            acc.w += wgt * f1.y;
            z += wgt;
        }
    }
    float inv = 1.f / z;
    float4 sk = *(const float4*)&g_sk[(size_t)n * 128 + lane * 4];
    float4 bb = *(const float4*)&bias[lane * 4];
    float4 sb = *(const float4*)&skb[lane * 4];
    float4 o;
    o.x = fmaxf(0.f, acc.x * inv + bb.x + sk.x + sb.x);
    o.y = fmaxf(0.f, acc.y * inv + bb.y + sk.y + sb.y);
    o.z = fmaxf(0.f, acc.z * inv + bb.z + sk.z + sb.z);
    o.w = fmaxf(0.f, acc.w * inv + bb.w + sk.w + sb.w);
    *(float4*)&g_x[(size_t)n * 128 + lane * 4] = o;
}

// ---------------- global max pool: 4 nodes/block, sorted batch --------------
__global__ void pool_k(const void* __restrict__ batch) {
    int base = blockIdx.x * 4;          // 12500 blocks
    int t = threadIdx.x;                // 128 features
    int is64 = g_is64;
    int cur = fetch_idx(batch, base, is64);
    float mx = g_x[(size_t)base * 128 + t];
#pragma unroll
    for (int i = 1; i < 4; ++i) {
        int n = base + i;
        if (n < NN) {
            int g = fetch_idx(batch, n, is64);
            float v = g_x[(size_t)n * 128 + t];
            if (g != cur) {
                atomicMax((int*)&g_pool[cur * 128 + t], __float_as_int(mx));
                cur = g; mx = v;
            } else {
                mx = fmaxf(mx, v);
            }
        }
    }
    atomicMax((int*)&g_pool[cur * 128 + t], __float_as_int(mx));
}

// ---------------- launch ------------------------------------------------------
extern "C" void kernel_launch(void* const* d_in, const int* in_sizes, int n_in,
                              void* d_out, int out_size) {
    const float* x     = (const float*)d_in[0];
    const void*  ei    = d_in[1];
    const void*  batch = d_in[2];
    const float* w[3]   = {(const float*)d_in[3],  (const float*)d_in[9],  (const float*)d_in[15]};
    const float* as_[3] = {(const float*)d_in[4],  (const float*)d_in[10], (const float*)d_in[16]};
    const float* ad_[3] = {(const float*)d_in[5],  (const float*)d_in[11], (const float*)d_in[17]};
    const float* b[3]   = {(const float*)d_in[6],  (const float*)d_in[12], (const float*)d_in[18]};
    const float* skw[3] = {(const float*)d_in[7],  (const float*)d_in[13], (const float*)d_in[19]};
    const float* skb[3] = {(const float*)d_in[8],  (const float*)d_in[14], (const float*)d_in[20]};
    const float* m1w = (const float*)d_in[21];
    const float* m1b = (const float*)d_in[22];
    const float* m2w = (const float*)d_in[23];
    const float* m2b = (const float*)d_in[24];
    float* out = (float*)d_out;

    float *px, *ppool, *phid;
    cudaGetSymbolAddress((void**)&px,    g_x);
    cudaGetSymbolAddress((void**)&ppool, g_pool);
    cudaGetSymbolAddress((void**)&phid,  g_hid);
    __half *pwh, *pwl, *pm1h, *pm1l, *pm2h, *pm2l;
    cudaGetSymbolAddress((void**)&pwh,  g_wthi);
    cudaGetSymbolAddress((void**)&pwl,  g_wtlo);
    cudaGetSymbolAddress((void**)&pm1h, g_m1hi);
    cudaGetSymbolAddress((void**)&pm1l, g_m1lo);
    cudaGetSymbolAddress((void**)&pm2h, g_m2hi);
    cudaGetSymbolAddress((void**)&pm2l, g_m2lo);

    static cudaStream_t s2 = 0;
    static cudaEvent_t evF = 0, evJ = 0;
    if (!s2) {
        cudaStreamCreateWithFlags(&s2, cudaStreamNonBlocking);
        cudaEventCreateWithFlags(&evF, cudaEventDisableTiming);
        cudaEventCreateWithFlags(&evJ, cudaEventDisableTiming);
    }
    cudaFuncSetAttribute(gemm_mma_k, cudaFuncAttributeMaxDynamicSharedMemorySize,
                         SM_TOT);
    cudaFuncSetAttribute(mlp_gemm_k, cudaFuncAttributeMaxDynamicSharedMemorySize,
                         SMM_TOT);

    const int SCAN_BLOCKS = (NN + 1023) / 1024;   // 49

    // fork: CSR build + MLP weight prep on s2 overlap GAT prep/gemm on origin.
    cudaEventRecord(evF, 0);
    cudaStreamWaitEvent(s2, evF, 0);

    detect_k<<<1, 1, 0, s2>>>((const unsigned*)ei);
    init_k<<<(NN + 255) / 256, 256, 0, s2>>>();
    prep_w_k<<<6, 256>>>(w[0], skw[0], w[1], skw[1], w[2], skw[2]);

    dim3 ggrid((NN + 127) / 128, 2);
    gemm_mma_k<<<ggrid, 256, SM_TOT>>>(
        x, pwh, pwl, pwh + 16384, pwl + 16384, as_[0], ad_[0], NN);

    hist_k<<<(EE + 255) / 256, 256, 0, s2>>>(ei);
    scan1_k<<<SCAN_BLOCKS, 1024, 0, s2>>>();
    scan2_k<<<1, 32, 0, s2>>>(SCAN_BLOCKS);
    scan3_k<<<SCAN_BLOCKS, 1024, 0, s2>>>();
    scatter_k<<<(ETOT + 255) / 256, 256, 0, s2>>>(ei);
    prep_mlp_k<<<8, 256, 0, s2>>>(m1w, m2w);
    cudaEventRecord(evJ, s2);

    cudaStreamWaitEvent(0, evJ, 0);   // CSR (+mlp weights) ready
    aggregate_k<<<(NN * 32 + 255) / 256, 256>>>(b[0], skb[0]);

    for (int L = 1; L < 3; ++L) {
        gemm_mma_k<<<ggrid, 256, SM_TOT>>>(
            px,
            pwh + (2 * L) * 16384,     pwl + (2 * L) * 16384,
            pwh + (2 * L + 1) * 16384, pwl + (2 * L + 1) * 16384,
            as_[L], ad_[L], NN);
        aggregate_k<<<(NN * 32 + 255) / 256, 256>>>(b[L], skb[L]);
    }

    pool_k<<<(NN + 3) / 4, 128>>>(batch);
    mlp_gemm_k<<<dim3(GG / 128, NHID / 128), 256, SMM_TOT>>>(
        ppool, pm1h, pm1l, m1b, phid, GG, NHID, HC, 1);
    mlp_gemm_k<<<dim3(GG / 128, NOUT / 128), 256, SMM_TOT>>>(
        phid, pm2h, pm2l, m2b, out, GG, NOUT, NHID, 0);
}